// round 10
// baseline (speedup 1.0000x reference)
#include <cuda_runtime.h>
#include <cuda_bf16.h>
#include <cstdint>
#include <cstddef>

#define BATCH 32
#define SEQ   512
#define ISZ   512
#define HSZ   1024
#define G4    4096
#define NB2   128
#define NT2   256

typedef unsigned long long ull;

// ---------------------------------------------------------------------------
// Device scratch (allocation-free rule: __device__ globals).
// g_Xg : [s][b][4096] input projections + bias, fp32, 256MB.
// g_h  : ping-pong hidden state, natural [b][k] layout.
// g_Upk: per-block smem image of packed U: [hb][p(512)][cgrp(8)][c(4)] ull,
//        where ull = {U[2p][col], U[2p+1][col]}, col = hb*8+(cgrp&1)*4+c,
//        gate = cgrp>>1. 16MB. Block hb copies its contiguous 128KB once.
// ---------------------------------------------------------------------------
__device__ float    g_Xg[(size_t)SEQ * BATCH * G4];
__device__ float    g_h[2][BATCH * HSZ];
__device__ ull      g_Upk[(size_t)128 * 16384];
__device__ unsigned g_cnt;

// ---------------------------------------------------------------------------
// f32x2 packed fp32 FMA (sm_100+): 2 MACs/instr.
// ---------------------------------------------------------------------------
__device__ __forceinline__ void fma2(ull& d, ull a, ull b) {
    asm("fma.rn.f32x2 %0, %1, %2, %0;" : "+l"(d) : "l"(a), "l"(b));
}
__device__ __forceinline__ ull pk2(float x, float y) {
    ull r; asm("mov.b64 %0, {%1, %2};" : "=l"(r) : "f"(x), "f"(y)); return r;
}
__device__ __forceinline__ float2 upk(ull v) {
    float2 r; asm("mov.b64 {%0, %1}, %2;" : "=f"(r.x), "=f"(r.y) : "l"(v)); return r;
}

// cp.async 16B, L1-bypass (.cg) — reads L2 directly (coherent with stcg writes).
__device__ __forceinline__ void cpa16(uint32_t saddr, const void* gptr) {
    asm volatile("cp.async.cg.shared.global [%0], [%1], 16;"
                 :: "r"(saddr), "l"(gptr) : "memory");
}
__device__ __forceinline__ void cpa_commit() {
    asm volatile("cp.async.commit_group;" ::: "memory");
}
__device__ __forceinline__ void cpa_wait1() {
    asm volatile("cp.async.wait_group 1;" ::: "memory");
}

// ---------------------------------------------------------------------------
// Init: zero h0 and barrier counter (runs every graph replay).
// ---------------------------------------------------------------------------
__global__ void lstm_init() {
    unsigned t = blockIdx.x * blockDim.x + threadIdx.x;
    if (t == 0) g_cnt = 0u;
    unsigned stride = gridDim.x * blockDim.x;
    for (unsigned i = t; i < BATCH * HSZ; i += stride) {
        g_h[0][i] = 0.f;
        g_h[1][i] = 0.f;
    }
}

// ---------------------------------------------------------------------------
// Pack U into the per-block smem image (see g_Upk comment).
// idx = hb*16384 + p*32 + cgrp*4 + c.
// ---------------------------------------------------------------------------
__global__ __launch_bounds__(256)
void pack_u(const float* __restrict__ u0, const float* __restrict__ u1,
            const float* __restrict__ u2, const float* __restrict__ u3)
{
    unsigned idx = blockIdx.x * 256u + threadIdx.x;     // 0 .. 2^21-1
    int c    = idx & 3;
    int cgrp = (idx >> 2) & 7;
    int p    = (idx >> 5) & 511;
    int hb   = idx >> 14;
    int gate = cgrp >> 1;
    int col  = hb * 8 + (cgrp & 1) * 4 + c;
    const float* u = (gate == 0) ? u0 : (gate == 1) ? u1 : (gate == 2) ? u2 : u3;
    g_Upk[idx] = pk2(u[(size_t)(2 * p) * HSZ + col],
                     u[(size_t)(2 * p + 1) * HSZ + col]);
}

// ---------------------------------------------------------------------------
// Phase 1: Xg = X @ [Wi|Wf|Wc|Wo] + b  (known-good; unchanged).
// ---------------------------------------------------------------------------
__global__ __launch_bounds__(256, 2)
void xg_gemm(const float* __restrict__ X,
             const float* __restrict__ w0, const float* __restrict__ w1,
             const float* __restrict__ w2, const float* __restrict__ w3,
             const float* __restrict__ bi0, const float* __restrict__ bi1,
             const float* __restrict__ bi2, const float* __restrict__ bi3)
{
    __shared__ float2 As2[16 * 128];
    __shared__ float  Bs [16 * 128];

    const int tid  = threadIdx.x;
    const int n0   = blockIdx.x * 128;
    const int m0   = blockIdx.y * 128;
    const int gate = blockIdx.x >> 3;
    const float* W  = (gate == 0) ? w0 : (gate == 1) ? w1 : (gate == 2) ? w2 : w3;
    const float* Bv = (gate == 0) ? bi0 : (gate == 1) ? bi1 : (gate == 2) ? bi2 : bi3;
    const int nloc = n0 & 1023;

    const int ar  = tid & 127;
    const int as4 = tid >> 7;
    const int mg  = m0 + ar;
    const float* Xrow = X + ((size_t)(mg & 31) * SEQ + (size_t)(mg >> 5)) * ISZ;

    const int bn4 = (tid & 31) * 4;
    const int bkr = tid >> 5;
    const int tx = tid & 15, ty = tid >> 4;

    ull acc[8][4];
    #pragma unroll
    for (int i = 0; i < 8; ++i)
        #pragma unroll
        for (int j = 0; j < 4; ++j) acc[i][j] = 0ULL;

    for (int kt = 0; kt < ISZ; kt += 16) {
        float4 a0 = *(const float4*)(Xrow + kt + as4 * 4);
        float4 a1 = *(const float4*)(Xrow + kt + (as4 + 2) * 4);
        float4 b0 = *(const float4*)(W + (size_t)(kt + bkr)     * HSZ + nloc + bn4);
        float4 b1 = *(const float4*)(W + (size_t)(kt + bkr + 8) * HSZ + nloc + bn4);

        __syncthreads();
        As2[(as4 * 4 + 0) * 128 + ar] = make_float2(a0.x, a0.x);
        As2[(as4 * 4 + 1) * 128 + ar] = make_float2(a0.y, a0.y);
        As2[(as4 * 4 + 2) * 128 + ar] = make_float2(a0.z, a0.z);
        As2[(as4 * 4 + 3) * 128 + ar] = make_float2(a0.w, a0.w);
        As2[((as4 + 2) * 4 + 0) * 128 + ar] = make_float2(a1.x, a1.x);
        As2[((as4 + 2) * 4 + 1) * 128 + ar] = make_float2(a1.y, a1.y);
        As2[((as4 + 2) * 4 + 2) * 128 + ar] = make_float2(a1.z, a1.z);
        As2[((as4 + 2) * 4 + 3) * 128 + ar] = make_float2(a1.w, a1.w);
        *(float4*)(Bs + bkr * 128 + bn4)       = b0;
        *(float4*)(Bs + (bkr + 8) * 128 + bn4) = b1;
        __syncthreads();

        #pragma unroll
        for (int k = 0; k < 16; ++k) {
            ull a[8], bb[4];
            ulonglong2 p;
            p = *(const ulonglong2*)(As2 + k * 128 + ty * 8);     a[0] = p.x; a[1] = p.y;
            p = *(const ulonglong2*)(As2 + k * 128 + ty * 8 + 2); a[2] = p.x; a[3] = p.y;
            p = *(const ulonglong2*)(As2 + k * 128 + ty * 8 + 4); a[4] = p.x; a[5] = p.y;
            p = *(const ulonglong2*)(As2 + k * 128 + ty * 8 + 6); a[6] = p.x; a[7] = p.y;
            p = *(const ulonglong2*)(Bs + k * 128 + tx * 8);      bb[0] = p.x; bb[1] = p.y;
            p = *(const ulonglong2*)(Bs + k * 128 + tx * 8 + 4);  bb[2] = p.x; bb[3] = p.y;
            #pragma unroll
            for (int i = 0; i < 8; ++i)
                #pragma unroll
                for (int j = 0; j < 4; ++j) fma2(acc[i][j], a[i], bb[j]);
        }
    }

    float4 bb0 = *(const float4*)(Bv + nloc + tx * 8);
    float4 bb1 = *(const float4*)(Bv + nloc + tx * 8 + 4);
    #pragma unroll
    for (int i = 0; i < 8; ++i) {
        float2 c0 = upk(acc[i][0]), c1 = upk(acc[i][1]);
        float2 c2 = upk(acc[i][2]), c3 = upk(acc[i][3]);
        float4 o0 = make_float4(c0.x + bb0.x, c0.y + bb0.y, c1.x + bb0.z, c1.y + bb0.w);
        float4 o1 = make_float4(c2.x + bb1.x, c2.y + bb1.y, c3.x + bb1.z, c3.y + bb1.w);
        size_t row = (size_t)(m0 + ty * 8 + i) * G4 + n0 + tx * 8;
        *(float4*)(g_Xg + row)     = o0;
        *(float4*)(g_Xg + row + 4) = o1;
    }
}

// ---------------------------------------------------------------------------
// Phase 2: persistent recurrence — U smem-resident edition.
// Block hb: 8 hidden units x 4 gates x 32 batches; thread (og, ks):
// og -> 4 batches (bg) x 4 cols (cgrp); ks -> k-range 256.
// U (128KB) loaded into smem ONCE; per step each ks warp-pair streams its
// 32KB h range in four 8KB cp.async chunks, double-buffered, synced with
// wait_group(1) + named barrier. Zero per-step U global traffic.
// smem: Us 128KB + Hbuf 4x2x8KB + Rs 16KB + Gs 4KB + XgS 8KB = 220KB.
// ---------------------------------------------------------------------------
#define SMEM_P2 ((32768 + 16384 + 4096 + 1024 + 2048) * 4)

// Stage chunk cidx of this ks range into h buffer buf (8KB, 8 cpa16/thread).
#define STAGE_CHUNK(buf, cidx) do {                                            \
    const float* hs_ = g_h[cur] + sb * 1024 + ks * 256 + (cidx) * 64;          \
    uint32_t db_ = HbA + (uint32_t)(((ks * 2 + (buf)) * 2048 + sb * 64) * 4);  \
    _Pragma("unroll")                                                          \
    for (int i_ = 0; i_ < 8; ++i_) {                                           \
        int g_  = sg0 + i_;                                                    \
        int sl_ = g_ ^ ((sb >> 2) & 7);                                        \
        cpa16(db_ + (uint32_t)(sl_ * 16), hs_ + g_ * 4);                       \
    }                                                                          \
} while (0)

// Compute chunk cidx (k window 64) from h buffer buf; U from smem.
#define COMPUTE_CHUNK(buf, cidx) do {                                          \
    const float* hb_ = sm + 32768 + (ks * 2 + (buf)) * 2048 + bg * 256;        \
    const ull*   ur_ = Us + (size_t)(ks * 128 + (cidx) * 32) * 32 + cgrp * 4;  \
    _Pragma("unroll")                                                          \
    for (int g_ = 0; g_ < 16; ++g_) {                                          \
        const ulonglong2* u0_ = (const ulonglong2*)(ur_ + (size_t)g_ * 64);    \
        const ulonglong2* u1_ = (const ulonglong2*)(ur_ + (size_t)g_ * 64 + 32);\
        ulonglong2 u00 = u0_[0], u01 = u0_[1];                                 \
        ulonglong2 u10 = u1_[0], u11 = u1_[1];                                 \
        int so_ = (g_ ^ bg) * 4;                                               \
        ulonglong2 h0 = *(const ulonglong2*)(hb_ + so_);                       \
        ulonglong2 h1 = *(const ulonglong2*)(hb_ + 64 + so_);                  \
        ulonglong2 h2 = *(const ulonglong2*)(hb_ + 128 + so_);                 \
        ulonglong2 h3 = *(const ulonglong2*)(hb_ + 192 + so_);                 \
        fma2(a00, h0.x, u00.x); fma2(a01, h0.x, u00.y);                        \
        fma2(a02, h0.x, u01.x); fma2(a03, h0.x, u01.y);                        \
        fma2(a10, h1.x, u00.x); fma2(a11, h1.x, u00.y);                        \
        fma2(a12, h1.x, u01.x); fma2(a13, h1.x, u01.y);                        \
        fma2(a20, h2.x, u00.x); fma2(a21, h2.x, u00.y);                        \
        fma2(a22, h2.x, u01.x); fma2(a23, h2.x, u01.y);                        \
        fma2(a30, h3.x, u00.x); fma2(a31, h3.x, u00.y);                        \
        fma2(a32, h3.x, u01.x); fma2(a33, h3.x, u01.y);                        \
        fma2(a00, h0.y, u10.x); fma2(a01, h0.y, u10.y);                        \
        fma2(a02, h0.y, u11.x); fma2(a03, h0.y, u11.y);                        \
        fma2(a10, h1.y, u10.x); fma2(a11, h1.y, u10.y);                        \
        fma2(a12, h1.y, u11.x); fma2(a13, h1.y, u11.y);                        \
        fma2(a20, h2.y, u10.x); fma2(a21, h2.y, u10.y);                        \
        fma2(a22, h2.y, u11.x); fma2(a23, h2.y, u11.y);                        \
        fma2(a30, h3.y, u10.x); fma2(a31, h3.y, u10.y);                        \
        fma2(a32, h3.y, u11.x); fma2(a33, h3.y, u11.y);                        \
    }                                                                          \
} while (0)

__global__ __launch_bounds__(NT2, 1)
void lstm_rec(float* __restrict__ out)
{
    extern __shared__ float sm[];
    ull*   Us  = (ull*)sm;                         // 16384 ull = 128KB
    float* Rs  = sm + 32768 + 16384;               // [ks][1024] partials
    float* Gs  = Rs + 4096;                        // [b][32]
    float* XgS = Gs + 1024;                        // 2 x [b][32]

    const int tid = threadIdx.x;
    const int hb  = blockIdx.x;

    // compute role
    const int og   = tid & 63;
    const int ks   = tid >> 6;
    const int bg   = og & 7;
    const int cgrp = og >> 3;

    // h staging role within ks pair: batch sb, granule half sg0
    const int t64 = tid & 63;
    const int sb  = t64 >> 1;
    const int sg0 = (t64 & 1) * 8;

    // epilogue role
    const int ub = tid >> 3;
    const int j  = tid & 7;
    const int kglob = hb * 8 + j;
    float creg = 0.f;

    // Xg staging role
    const int xb = tid >> 3, xq = tid & 7;
    const size_t xgcol = (size_t)(xq >> 1) * 1024 + hb * 8 + (xq & 1) * 4;

    const uint32_t HbA = (uint32_t)__cvta_generic_to_shared(sm + 32768);
    const uint32_t XgA = (uint32_t)__cvta_generic_to_shared(XgS);

    float* out_h = out + (size_t)BATCH * SEQ * HSZ;
    float* out_c = out_h + BATCH * HSZ;

    // --- one-time: load this block's U slice (128KB) into smem ---
    {
        const float4* src = (const float4*)(g_Upk + (size_t)hb * 16384);
        float4* dst = (float4*)Us;
        #pragma unroll 8
        for (int i = tid; i < 8192; i += NT2) dst[i] = src[i];
    }
    __syncthreads();

    // prologue: Xg slice for step 0 into buffer 0
    cpa16(XgA + (uint32_t)((xb * 32 + xq * 4) * 4),
          g_Xg + (size_t)xb * G4 + xgcol);
    cpa_commit();

    int cur = 0;
    for (int s = 0; s < SEQ; ++s) {
        // stage chunks 0,1 of this step's h (after grid barrier => g_h[cur] valid)
        STAGE_CHUNK(0, 0); cpa_commit();
        STAGE_CHUNK(1, 1); cpa_commit();

        ull a00 = 0, a01 = 0, a02 = 0, a03 = 0;
        ull a10 = 0, a11 = 0, a12 = 0, a13 = 0;
        ull a20 = 0, a21 = 0, a22 = 0, a23 = 0;
        ull a30 = 0, a31 = 0, a32 = 0, a33 = 0;

        #pragma unroll 1
        for (int c = 0; c < 4; ++c) {
            cpa_wait1();                                   // chunk c landed
            asm volatile("bar.sync %0, 64;" :: "r"(1 + ks) : "memory");
            COMPUTE_CHUNK(c & 1, c);
            if (c == 0) {
                STAGE_CHUNK(0, 2);
                int sn = (s + 1 < SEQ) ? s + 1 : SEQ - 1;  // next-step Xg
                cpa16(XgA + (uint32_t)((((s + 1) & 1) * 1024 + xb * 32 + xq * 4) * 4),
                      g_Xg + ((size_t)sn * BATCH + xb) * G4 + xgcol);
            } else if (c == 1) {
                STAGE_CHUNK(1, 3);
            }
            cpa_commit();                                  // empty group ok
        }

        // --- write split-K partials (sum pair halves) ---
        {
            float* r = Rs + ks * 1024 + og * 16;
            float2 t;
            t = upk(a00); r[0]  = t.x + t.y;  t = upk(a01); r[1]  = t.x + t.y;
            t = upk(a02); r[2]  = t.x + t.y;  t = upk(a03); r[3]  = t.x + t.y;
            t = upk(a10); r[4]  = t.x + t.y;  t = upk(a11); r[5]  = t.x + t.y;
            t = upk(a12); r[6]  = t.x + t.y;  t = upk(a13); r[7]  = t.x + t.y;
            t = upk(a20); r[8]  = t.x + t.y;  t = upk(a21); r[9]  = t.x + t.y;
            t = upk(a22); r[10] = t.x + t.y;  t = upk(a23); r[11] = t.x + t.y;
            t = upk(a30); r[12] = t.x + t.y;  t = upk(a31); r[13] = t.x + t.y;
            t = upk(a32); r[14] = t.x + t.y;  t = upk(a33); r[15] = t.x + t.y;
        }
        __syncthreads();

        // --- reduce 4 partials + add Xg (smem) -> Gs[b][c] ---
        const float* Xcur = XgS + (s & 1) * 1024;
        #pragma unroll
        for (int i = 0; i < 4; ++i) {
            int o   = tid * 4 + i;
            int oog = o >> 4, li = o & 15;
            int bb  = (oog & 7) * 4 + (li >> 2);
            int cc  = (oog >> 3) * 4 + (li & 3);
            float v = Rs[o] + Rs[1024 + o] + Rs[2048 + o] + Rs[3072 + o];
            v += Xcur[bb * 32 + cc];
            Gs[bb * 32 + cc] = v;
        }
        __syncthreads();

        // --- gates + state update (role: ub, j) ---
        {
            float gi = Gs[ub * 32 + j];
            float gf = Gs[ub * 32 + 8 + j];
            float gc = Gs[ub * 32 + 16 + j];
            float go = Gs[ub * 32 + 24 + j];
            float it = 1.f / (1.f + __expf(-gi));
            float ft = 1.f / (1.f + __expf(-gf));
            float ct = tanhf(gc);
            float ot = 1.f / (1.f + __expf(-go));
            creg = ft * creg + it * ct;
            float hn = ot * tanhf(creg);
            __stcg(&g_h[cur ^ 1][ub * HSZ + kglob], hn);
            out[((size_t)ub * SEQ + s) * HSZ + kglob] = hn;
            if (s == SEQ - 1) {
                out_h[ub * HSZ + kglob] = hn;
                out_c[ub * HSZ + kglob] = creg;
            }
        }

        // --- grid barrier: release-add + acquire-spin ---
        __syncthreads();
        if (tid == 0) {
            unsigned old;
            asm volatile("atom.add.release.gpu.u32 %0, [%1], 1;"
                         : "=r"(old) : "l"(&g_cnt) : "memory");
            unsigned target = (unsigned)NB2 * (unsigned)(s + 1);
            unsigned v;
            do {
                asm volatile("ld.acquire.gpu.u32 %0, [%1];"
                             : "=r"(v) : "l"(&g_cnt) : "memory");
            } while (v < target);
        }
        __syncthreads();
        cur ^= 1;
    }
}

// ---------------------------------------------------------------------------
// Launch. Inputs: X, w_i,u_i,b_i, w_f,u_f,b_f, w_c,u_c,b_c, w_o,u_o,b_o.
// Output: [hidden_seq (B,S,H) | h_T (B,H) | c_T (B,H)] fp32.
// ---------------------------------------------------------------------------
extern "C" void kernel_launch(void* const* d_in, const int* in_sizes, int n_in,
                              void* d_out, int out_size) {
    (void)in_sizes; (void)n_in; (void)out_size;
    const float* X   = (const float*)d_in[0];
    const float* w_i = (const float*)d_in[1];
    const float* u_i = (const float*)d_in[2];
    const float* b_i = (const float*)d_in[3];
    const float* w_f = (const float*)d_in[4];
    const float* u_f = (const float*)d_in[5];
    const float* b_f = (const float*)d_in[6];
    const float* w_c = (const float*)d_in[7];
    const float* u_c = (const float*)d_in[8];
    const float* b_c = (const float*)d_in[9];
    const float* w_o = (const float*)d_in[10];
    const float* u_o = (const float*)d_in[11];
    const float* b_o = (const float*)d_in[12];
    float* out = (float*)d_out;

    lstm_init<<<64, 256>>>();
    pack_u<<<8192, 256>>>(u_i, u_f, u_c, u_o);

    dim3 g1(32, 128);   // N/128 x M/128
    xg_gemm<<<g1, 256>>>(X, w_i, w_f, w_c, w_o, b_i, b_f, b_c, b_o);

    cudaFuncSetAttribute(lstm_rec, cudaFuncAttributeMaxDynamicSharedMemorySize,
                         SMEM_P2);
    lstm_rec<<<NB2, NT2, SMEM_P2>>>(out);
}

// round 11
// speedup vs baseline: 1.2707x; 1.2707x over previous
#include <cuda_runtime.h>
#include <cuda_bf16.h>
#include <cstdint>
#include <cstddef>

#define BATCH 32
#define SEQ   512
#define ISZ   512
#define HSZ   1024
#define G4    4096
#define NB2   128
#define NT2   256

typedef unsigned long long ull;

// ---------------------------------------------------------------------------
// Device scratch (allocation-free rule: __device__ globals).
// g_Xg : [s][b][4096] input projections + bias, fp32, 256MB.
// g_h  : ping-pong hidden state, natural [b][k] layout.
// g_Upk: per-block image of packed U: [hb][p(512)][cgrp(8)][c(4)] ull,
//        ull = {U[2p][col], U[2p+1][col]}, col = hb*8+(cgrp&1)*4+c,
//        gate = cgrp>>1. 16MB. Block hb copies its contiguous 128KB once.
// ---------------------------------------------------------------------------
__device__ float    g_Xg[(size_t)SEQ * BATCH * G4];
__device__ float    g_h[2][BATCH * HSZ];
__device__ ull      g_Upk[(size_t)128 * 16384];
__device__ unsigned g_cnt;

// ---------------------------------------------------------------------------
// f32x2 packed fp32 FMA (sm_100+): 2 MACs/instr.
// ---------------------------------------------------------------------------
__device__ __forceinline__ void fma2(ull& d, ull a, ull b) {
    asm("fma.rn.f32x2 %0, %1, %2, %0;" : "+l"(d) : "l"(a), "l"(b));
}
__device__ __forceinline__ ull pk2(float x, float y) {
    ull r; asm("mov.b64 %0, {%1, %2};" : "=l"(r) : "f"(x), "f"(y)); return r;
}
__device__ __forceinline__ float2 upk(ull v) {
    float2 r; asm("mov.b64 {%0, %1}, %2;" : "=f"(r.x), "=f"(r.y) : "l"(v)); return r;
}

// cp.async 16B, L1-bypass (.cg) — reads L2 directly (coherent with stcg writes).
__device__ __forceinline__ void cpa16(uint32_t saddr, const void* gptr) {
    asm volatile("cp.async.cg.shared.global [%0], [%1], 16;"
                 :: "r"(saddr), "l"(gptr) : "memory");
}
__device__ __forceinline__ void cpa_commit() {
    asm volatile("cp.async.commit_group;" ::: "memory");
}
__device__ __forceinline__ void cpa_wait1() {
    asm volatile("cp.async.wait_group 1;" ::: "memory");
}
__device__ __forceinline__ void cpa_wait0() {
    asm volatile("cp.async.wait_group 0;" ::: "memory");
}

// ---------------------------------------------------------------------------
// Init: zero h0 and barrier counter (runs every graph replay).
// ---------------------------------------------------------------------------
__global__ void lstm_init() {
    unsigned t = blockIdx.x * blockDim.x + threadIdx.x;
    if (t == 0) g_cnt = 0u;
    unsigned stride = gridDim.x * blockDim.x;
    for (unsigned i = t; i < BATCH * HSZ; i += stride) {
        g_h[0][i] = 0.f;
        g_h[1][i] = 0.f;
    }
}

// ---------------------------------------------------------------------------
// Pack U into the per-block image (see g_Upk comment).
// idx = hb*16384 + p*32 + cgrp*4 + c.
// ---------------------------------------------------------------------------
__global__ __launch_bounds__(256)
void pack_u(const float* __restrict__ u0, const float* __restrict__ u1,
            const float* __restrict__ u2, const float* __restrict__ u3)
{
    unsigned idx = blockIdx.x * 256u + threadIdx.x;     // 0 .. 2^21-1
    int c    = idx & 3;
    int cgrp = (idx >> 2) & 7;
    int p    = (idx >> 5) & 511;
    int hb   = idx >> 14;
    int gate = cgrp >> 1;
    int col  = hb * 8 + (cgrp & 1) * 4 + c;
    const float* u = (gate == 0) ? u0 : (gate == 1) ? u1 : (gate == 2) ? u2 : u3;
    g_Upk[idx] = pk2(u[(size_t)(2 * p) * HSZ + col],
                     u[(size_t)(2 * p + 1) * HSZ + col]);
}

// ---------------------------------------------------------------------------
// Phase 1: Xg = X @ [Wi|Wf|Wc|Wo] + b  (known-good; unchanged).
// ---------------------------------------------------------------------------
__global__ __launch_bounds__(256, 2)
void xg_gemm(const float* __restrict__ X,
             const float* __restrict__ w0, const float* __restrict__ w1,
             const float* __restrict__ w2, const float* __restrict__ w3,
             const float* __restrict__ bi0, const float* __restrict__ bi1,
             const float* __restrict__ bi2, const float* __restrict__ bi3)
{
    __shared__ float2 As2[16 * 128];
    __shared__ float  Bs [16 * 128];

    const int tid  = threadIdx.x;
    const int n0   = blockIdx.x * 128;
    const int m0   = blockIdx.y * 128;
    const int gate = blockIdx.x >> 3;
    const float* W  = (gate == 0) ? w0 : (gate == 1) ? w1 : (gate == 2) ? w2 : w3;
    const float* Bv = (gate == 0) ? bi0 : (gate == 1) ? bi1 : (gate == 2) ? bi2 : bi3;
    const int nloc = n0 & 1023;

    const int ar  = tid & 127;
    const int as4 = tid >> 7;
    const int mg  = m0 + ar;
    const float* Xrow = X + ((size_t)(mg & 31) * SEQ + (size_t)(mg >> 5)) * ISZ;

    const int bn4 = (tid & 31) * 4;
    const int bkr = tid >> 5;
    const int tx = tid & 15, ty = tid >> 4;

    ull acc[8][4];
    #pragma unroll
    for (int i = 0; i < 8; ++i)
        #pragma unroll
        for (int j = 0; j < 4; ++j) acc[i][j] = 0ULL;

    for (int kt = 0; kt < ISZ; kt += 16) {
        float4 a0 = *(const float4*)(Xrow + kt + as4 * 4);
        float4 a1 = *(const float4*)(Xrow + kt + (as4 + 2) * 4);
        float4 b0 = *(const float4*)(W + (size_t)(kt + bkr)     * HSZ + nloc + bn4);
        float4 b1 = *(const float4*)(W + (size_t)(kt + bkr + 8) * HSZ + nloc + bn4);

        __syncthreads();
        As2[(as4 * 4 + 0) * 128 + ar] = make_float2(a0.x, a0.x);
        As2[(as4 * 4 + 1) * 128 + ar] = make_float2(a0.y, a0.y);
        As2[(as4 * 4 + 2) * 128 + ar] = make_float2(a0.z, a0.z);
        As2[(as4 * 4 + 3) * 128 + ar] = make_float2(a0.w, a0.w);
        As2[((as4 + 2) * 4 + 0) * 128 + ar] = make_float2(a1.x, a1.x);
        As2[((as4 + 2) * 4 + 1) * 128 + ar] = make_float2(a1.y, a1.y);
        As2[((as4 + 2) * 4 + 2) * 128 + ar] = make_float2(a1.z, a1.z);
        As2[((as4 + 2) * 4 + 3) * 128 + ar] = make_float2(a1.w, a1.w);
        *(float4*)(Bs + bkr * 128 + bn4)       = b0;
        *(float4*)(Bs + (bkr + 8) * 128 + bn4) = b1;
        __syncthreads();

        #pragma unroll
        for (int k = 0; k < 16; ++k) {
            ull a[8], bb[4];
            ulonglong2 p;
            p = *(const ulonglong2*)(As2 + k * 128 + ty * 8);     a[0] = p.x; a[1] = p.y;
            p = *(const ulonglong2*)(As2 + k * 128 + ty * 8 + 2); a[2] = p.x; a[3] = p.y;
            p = *(const ulonglong2*)(As2 + k * 128 + ty * 8 + 4); a[4] = p.x; a[5] = p.y;
            p = *(const ulonglong2*)(As2 + k * 128 + ty * 8 + 6); a[6] = p.x; a[7] = p.y;
            p = *(const ulonglong2*)(Bs + k * 128 + tx * 8);      bb[0] = p.x; bb[1] = p.y;
            p = *(const ulonglong2*)(Bs + k * 128 + tx * 8 + 4);  bb[2] = p.x; bb[3] = p.y;
            #pragma unroll
            for (int i = 0; i < 8; ++i)
                #pragma unroll
                for (int j = 0; j < 4; ++j) fma2(acc[i][j], a[i], bb[j]);
        }
    }

    float4 bb0 = *(const float4*)(Bv + nloc + tx * 8);
    float4 bb1 = *(const float4*)(Bv + nloc + tx * 8 + 4);
    #pragma unroll
    for (int i = 0; i < 8; ++i) {
        float2 c0 = upk(acc[i][0]), c1 = upk(acc[i][1]);
        float2 c2 = upk(acc[i][2]), c3 = upk(acc[i][3]);
        float4 o0 = make_float4(c0.x + bb0.x, c0.y + bb0.y, c1.x + bb0.z, c1.y + bb0.w);
        float4 o1 = make_float4(c2.x + bb1.x, c2.y + bb1.y, c3.x + bb1.z, c3.y + bb1.w);
        size_t row = (size_t)(m0 + ty * 8 + i) * G4 + n0 + tx * 8;
        *(float4*)(g_Xg + row)     = o0;
        *(float4*)(g_Xg + row + 4) = o1;
    }
}

// ---------------------------------------------------------------------------
// Phase 2: persistent recurrence — U smem-resident, coalesced h staging.
// Block hb: 8 hidden units x 4 gates x 32 batches; thread (og, ks):
// og -> 4 batches (bg) x 4 cols (cgrp); ks -> k-range 256.
// U (128KB) loaded into smem ONCE. Per step each ks warp-pair streams its
// 32KB h range as four 8KB chunks through TWO smem buffers; a pair barrier
// after each compute closes the WAR window before the buffer is re-staged.
// Staging lanes are k-contiguous (4 L1 wavefronts / cp.async instr).
// smem: Us 128KB + Hbuf 4x2x8KB + Rs 16KB + Gs 4KB + XgS 8KB = 220KB.
// ---------------------------------------------------------------------------
#define SMEM_P2 ((32768 + 16384 + 4096 + 1024 + 2048) * 4)

// Stage chunk cidx of this ks k-range into pair buffer buf.
// Thread t64 (0..63), iter i_: id = i_*64+t64; b = id>>4, g = id&15.
// src lanes contiguous in g (256B runs); dst slot = g ^ (b>>2) (compute swizzle).
#define STAGE_CHUNK(buf, cidx) do {                                            \
    const float* hs_ = g_h[cur] + ks * 256 + (cidx) * 64;                      \
    uint32_t db_ = HbA + (uint32_t)(((ks * 2 + (buf)) * 2048) * 4);            \
    _Pragma("unroll")                                                          \
    for (int i_ = 0; i_ < 8; ++i_) {                                           \
        int id_ = i_ * 64 + t64;                                               \
        int b_  = id_ >> 4;                                                    \
        int g_  = id_ & 15;                                                    \
        int sl_ = g_ ^ (b_ >> 2);                                              \
        cpa16(db_ + (uint32_t)((b_ * 64 + sl_ * 4) * 4),                       \
              hs_ + (size_t)b_ * 1024 + g_ * 4);                               \
    }                                                                          \
} while (0)

// Compute chunk cidx (k window 64) from pair buffer buf; U from smem.
#define COMPUTE_CHUNK(buf, cidx) do {                                          \
    const float* hb_ = sm + 32768 + (ks * 2 + (buf)) * 2048 + bg * 256;        \
    const ull*   ur_ = Us + (size_t)(ks * 128 + (cidx) * 32) * 32 + cgrp * 4;  \
    _Pragma("unroll")                                                          \
    for (int g_ = 0; g_ < 16; ++g_) {                                          \
        const ulonglong2* u0_ = (const ulonglong2*)(ur_ + (size_t)g_ * 64);    \
        const ulonglong2* u1_ = (const ulonglong2*)(ur_ + (size_t)g_ * 64 + 32);\
        ulonglong2 u00 = u0_[0], u01 = u0_[1];                                 \
        ulonglong2 u10 = u1_[0], u11 = u1_[1];                                 \
        int so_ = (g_ ^ bg) * 4;                                               \
        ulonglong2 h0 = *(const ulonglong2*)(hb_ + so_);                       \
        ulonglong2 h1 = *(const ulonglong2*)(hb_ + 64 + so_);                  \
        ulonglong2 h2 = *(const ulonglong2*)(hb_ + 128 + so_);                 \
        ulonglong2 h3 = *(const ulonglong2*)(hb_ + 192 + so_);                 \
        fma2(a00, h0.x, u00.x); fma2(a01, h0.x, u00.y);                        \
        fma2(a02, h0.x, u01.x); fma2(a03, h0.x, u01.y);                        \
        fma2(a10, h1.x, u00.x); fma2(a11, h1.x, u00.y);                        \
        fma2(a12, h1.x, u01.x); fma2(a13, h1.x, u01.y);                        \
        fma2(a20, h2.x, u00.x); fma2(a21, h2.x, u00.y);                        \
        fma2(a22, h2.x, u01.x); fma2(a23, h2.x, u01.y);                        \
        fma2(a30, h3.x, u00.x); fma2(a31, h3.x, u00.y);                        \
        fma2(a32, h3.x, u01.x); fma2(a33, h3.x, u01.y);                        \
        fma2(a00, h0.y, u10.x); fma2(a01, h0.y, u10.y);                        \
        fma2(a02, h0.y, u11.x); fma2(a03, h0.y, u11.y);                        \
        fma2(a10, h1.y, u10.x); fma2(a11, h1.y, u10.y);                        \
        fma2(a12, h1.y, u11.x); fma2(a13, h1.y, u11.y);                        \
        fma2(a20, h2.y, u10.x); fma2(a21, h2.y, u10.y);                        \
        fma2(a22, h2.y, u11.x); fma2(a23, h2.y, u11.y);                        \
        fma2(a30, h3.y, u10.x); fma2(a31, h3.y, u10.y);                        \
        fma2(a32, h3.y, u11.x); fma2(a33, h3.y, u11.y);                        \
    }                                                                          \
} while (0)

#define PAIR_BAR() asm volatile("bar.sync %0, 64;" :: "r"(1 + ks) : "memory")

__global__ __launch_bounds__(NT2, 1)
void lstm_rec(float* __restrict__ out)
{
    extern __shared__ float sm[];
    ull*   Us  = (ull*)sm;                         // 16384 ull = 128KB
    float* Rs  = sm + 32768 + 16384;               // [ks][1024] partials
    float* Gs  = Rs + 4096;                        // [b][32]
    float* XgS = Gs + 1024;                        // 2 x [b][32]

    const int tid = threadIdx.x;
    const int hb  = blockIdx.x;

    // compute role
    const int og   = tid & 63;
    const int ks   = tid >> 6;
    const int bg   = og & 7;
    const int cgrp = og >> 3;
    const int t64  = tid & 63;

    // epilogue role
    const int ub = tid >> 3;
    const int j  = tid & 7;
    const int kglob = hb * 8 + j;
    float creg = 0.f;

    // Xg staging role
    const int xb = tid >> 3, xq = tid & 7;
    const size_t xgcol = (size_t)(xq >> 1) * 1024 + hb * 8 + (xq & 1) * 4;

    const uint32_t HbA = (uint32_t)__cvta_generic_to_shared(sm + 32768);
    const uint32_t XgA = (uint32_t)__cvta_generic_to_shared(XgS);

    float* out_h = out + (size_t)BATCH * SEQ * HSZ;
    float* out_c = out_h + BATCH * HSZ;

    // --- one-time: load this block's U slice (128KB) into smem ---
    {
        const float4* src = (const float4*)(g_Upk + (size_t)hb * 16384);
        float4* dst = (float4*)Us;
        #pragma unroll 8
        for (int i = tid; i < 8192; i += NT2) dst[i] = src[i];
    }
    __syncthreads();

    // prologue: Xg slice for step 0 into buffer 0 (folded into step-0 G1 wait)
    int cur = 0;
    for (int s = 0; s < SEQ; ++s) {
        // stage chunks 0,1 (grid barrier at prev step end => g_h[cur] valid)
        STAGE_CHUNK(0, 0);
        if (s == 0)
            cpa16(XgA + (uint32_t)((xb * 32 + xq * 4) * 4),
                  g_Xg + (size_t)xb * G4 + xgcol);
        cpa_commit();                                   // G1 = c0 (+X0 first)
        STAGE_CHUNK(1, 1); cpa_commit();                // G2 = c1

        ull a00 = 0, a01 = 0, a02 = 0, a03 = 0;
        ull a10 = 0, a11 = 0, a12 = 0, a13 = 0;
        ull a20 = 0, a21 = 0, a22 = 0, a23 = 0;
        ull a30 = 0, a31 = 0, a32 = 0, a33 = 0;

        // c=0: wait G1, compute buf0, close WAR, restage c2 (+ next Xg)  -> G3
        cpa_wait1(); PAIR_BAR();
        COMPUTE_CHUNK(0, 0);
        PAIR_BAR();
        STAGE_CHUNK(0, 2);
        {
            int sn = (s + 1 < SEQ) ? s + 1 : SEQ - 1;
            cpa16(XgA + (uint32_t)((((s + 1) & 1) * 1024 + xb * 32 + xq * 4) * 4),
                  g_Xg + ((size_t)sn * BATCH + xb) * G4 + xgcol);
        }
        cpa_commit();                                   // G3 = c2 + X_{s+1}

        // c=1: wait G2, compute buf1, close WAR, restage c3              -> G4
        cpa_wait1(); PAIR_BAR();
        COMPUTE_CHUNK(1, 1);
        PAIR_BAR();
        STAGE_CHUNK(1, 3); cpa_commit();                // G4 = c3

        // c=2: wait G3 (c2 + Xg), compute buf0
        cpa_wait1(); PAIR_BAR();
        COMPUTE_CHUNK(0, 2);

        // c=3: wait G4, compute buf1
        cpa_wait0(); PAIR_BAR();
        COMPUTE_CHUNK(1, 3);

        // --- write split-K partials (sum pair halves) ---
        {
            float* r = Rs + ks * 1024 + og * 16;
            float2 t;
            t = upk(a00); r[0]  = t.x + t.y;  t = upk(a01); r[1]  = t.x + t.y;
            t = upk(a02); r[2]  = t.x + t.y;  t = upk(a03); r[3]  = t.x + t.y;
            t = upk(a10); r[4]  = t.x + t.y;  t = upk(a11); r[5]  = t.x + t.y;
            t = upk(a12); r[6]  = t.x + t.y;  t = upk(a13); r[7]  = t.x + t.y;
            t = upk(a20); r[8]  = t.x + t.y;  t = upk(a21); r[9]  = t.x + t.y;
            t = upk(a22); r[10] = t.x + t.y;  t = upk(a23); r[11] = t.x + t.y;
            t = upk(a30); r[12] = t.x + t.y;  t = upk(a31); r[13] = t.x + t.y;
            t = upk(a32); r[14] = t.x + t.y;  t = upk(a33); r[15] = t.x + t.y;
        }
        __syncthreads();

        // --- reduce 4 partials + add Xg (smem) -> Gs[b][c] ---
        const float* Xcur = XgS + (s & 1) * 1024;
        #pragma unroll
        for (int i = 0; i < 4; ++i) {
            int o   = tid * 4 + i;
            int oog = o >> 4, li = o & 15;
            int bb  = (oog & 7) * 4 + (li >> 2);
            int cc  = (oog >> 3) * 4 + (li & 3);
            float v = Rs[o] + Rs[1024 + o] + Rs[2048 + o] + Rs[3072 + o];
            v += Xcur[bb * 32 + cc];
            Gs[bb * 32 + cc] = v;
        }
        __syncthreads();

        // --- gates + state update (role: ub, j) ---
        {
            float gi = Gs[ub * 32 + j];
            float gf = Gs[ub * 32 + 8 + j];
            float gc = Gs[ub * 32 + 16 + j];
            float go = Gs[ub * 32 + 24 + j];
            float it = 1.f / (1.f + __expf(-gi));
            float ft = 1.f / (1.f + __expf(-gf));
            float ct = tanhf(gc);
            float ot = 1.f / (1.f + __expf(-go));
            creg = ft * creg + it * ct;
            float hn = ot * tanhf(creg);
            __stcg(&g_h[cur ^ 1][ub * HSZ + kglob], hn);
            out[((size_t)ub * SEQ + s) * HSZ + kglob] = hn;
            if (s == SEQ - 1) {
                out_h[ub * HSZ + kglob] = hn;
                out_c[ub * HSZ + kglob] = creg;
            }
        }

        // --- grid barrier: release-add + acquire-spin ---
        __syncthreads();
        if (tid == 0) {
            unsigned old;
            asm volatile("atom.add.release.gpu.u32 %0, [%1], 1;"
                         : "=r"(old) : "l"(&g_cnt) : "memory");
            unsigned target = (unsigned)NB2 * (unsigned)(s + 1);
            unsigned v;
            do {
                asm volatile("ld.acquire.gpu.u32 %0, [%1];"
                             : "=r"(v) : "l"(&g_cnt) : "memory");
            } while (v < target);
        }
        __syncthreads();
        cur ^= 1;
    }
}

// ---------------------------------------------------------------------------
// Launch. Inputs: X, w_i,u_i,b_i, w_f,u_f,b_f, w_c,u_c,b_c, w_o,u_o,b_o.
// Output: [hidden_seq (B,S,H) | h_T (B,H) | c_T (B,H)] fp32.
// ---------------------------------------------------------------------------
extern "C" void kernel_launch(void* const* d_in, const int* in_sizes, int n_in,
                              void* d_out, int out_size) {
    (void)in_sizes; (void)n_in; (void)out_size;
    const float* X   = (const float*)d_in[0];
    const float* w_i = (const float*)d_in[1];
    const float* u_i = (const float*)d_in[2];
    const float* b_i = (const float*)d_in[3];
    const float* w_f = (const float*)d_in[4];
    const float* u_f = (const float*)d_in[5];
    const float* b_f = (const float*)d_in[6];
    const float* w_c = (const float*)d_in[7];
    const float* u_c = (const float*)d_in[8];
    const float* b_c = (const float*)d_in[9];
    const float* w_o = (const float*)d_in[10];
    const float* u_o = (const float*)d_in[11];
    const float* b_o = (const float*)d_in[12];
    float* out = (float*)d_out;

    lstm_init<<<64, 256>>>();
    pack_u<<<8192, 256>>>(u_i, u_f, u_c, u_o);

    dim3 g1(32, 128);   // N/128 x M/128
    xg_gemm<<<g1, 256>>>(X, w_i, w_f, w_c, w_o, b_i, b_f, b_c, b_o);

    cudaFuncSetAttribute(lstm_rec, cudaFuncAttributeMaxDynamicSharedMemorySize,
                         SMEM_P2);
    lstm_rec<<<NB2, NT2, SMEM_P2>>>(out);
}